// round 6
// baseline (speedup 1.0000x reference)
#include <cuda_runtime.h>

#define N_VARS 2048
#define P      8
#define BATCH  4096
#define ROW    (N_VARS * P)      // 16384
#define COLS4  (N_VARS / 4)      // 512
#define THREADS 256

// 64 KB scratch for the gathered diagonal: diag[lag*N_VARS + i] = weight[i, lag*N_VARS + i]
__device__ float g_diag[P * N_VARS];

__global__ __launch_bounds__(128) void gather_diag_kernel(
    const float* __restrict__ weight)
{
    int idx = blockIdx.x * 128 + threadIdx.x;      // 0 .. 16383
    int lag = idx >> 11;                           // / N_VARS
    int i   = idx & (N_VARS - 1);                  // % N_VARS
    g_diag[idx] = __ldg(&weight[(size_t)i * ROW + lag * N_VARS + i]);

    // Fire the programmatic-launch trigger as soon as our store is issued,
    // so the dependent kernel's blocks start launching while this grid drains.
    cudaTriggerProgrammaticLaunchCompletion();
}

__global__ __launch_bounds__(THREADS) void diag_linear_kernel(
    const float4* __restrict__ x,    // (4096, 16384) as float4
    float4*       __restrict__ out)  // (4096, 2048)  as float4
{
    int tid = blockIdx.x * THREADS + threadIdx.x;  // 0 .. BATCH*COLS4-1
    int b = tid / COLS4;
    int c = tid - b * COLS4;

    const float4* xrow = x + (size_t)b * (ROW / 4);

    // ---- pre-issue all 8 x loads (independent of the gather kernel) ----
    float4 xv[P];
    #pragma unroll
    for (int lag = 0; lag < P; lag++)
        xv[lag] = __ldg(&xrow[lag * COLS4 + c]);

    // ---- PDL: wait for gather completion + memory visibility ----
    cudaGridDependencySynchronize();

    const float4* diag4 = reinterpret_cast<const float4*>(g_diag);
    float4 acc;
    acc.x = 0.f; acc.y = 0.f; acc.z = 0.f; acc.w = 0.f;

    #pragma unroll
    for (int lag = 0; lag < P; lag++) {
        float4 dv = diag4[lag * COLS4 + c];        // L2-hot, 64 KB working set
        acc.x = fmaf(xv[lag].x, dv.x, acc.x);
        acc.y = fmaf(xv[lag].y, dv.y, acc.y);
        acc.z = fmaf(xv[lag].z, dv.z, acc.z);
        acc.w = fmaf(xv[lag].w, dv.w, acc.w);
    }
    out[tid] = acc;
}

extern "C" void kernel_launch(void* const* d_in, const int* in_sizes, int n_in,
                              void* d_out, int out_size) {
    const float* x      = (const float*)d_in[0];   // (4096, 16384)
    const float* weight = (const float*)d_in[1];   // (2048, 16384)
    float* out          = (float*)d_out;           // (4096, 2048)

    // 1) gather diagonal: 128 blocks x 128 threads = 16384 elements
    gather_diag_kernel<<<(P * N_VARS) / 128, 128>>>(weight);

    // 2) main kernel with programmatic dependent launch
    cudaLaunchAttribute attrs[1];
    attrs[0].id = cudaLaunchAttributeProgrammaticStreamSerialization;
    attrs[0].val.programmaticStreamSerializationAllowed = 1;

    cudaLaunchConfig_t cfg = {};
    cfg.gridDim  = dim3((BATCH * COLS4) / THREADS, 1, 1);  // 8192 blocks
    cfg.blockDim = dim3(THREADS, 1, 1);
    cfg.dynamicSmemBytes = 0;
    cfg.stream   = 0;
    cfg.attrs    = attrs;
    cfg.numAttrs = 1;

    cudaLaunchKernelEx(&cfg, diag_linear_kernel,
                       reinterpret_cast<const float4*>(x),
                       reinterpret_cast<float4*>(out));
}